// round 6
// baseline (speedup 1.0000x reference)
#include <cuda_runtime.h>

// SSN superpixel EM, sparse 9-neighborhood formulation.
// Geometry fixed by the problem: B=4, H=W=256, C=20, 16x16 superpixel grid,
// cell=16x16 pixels, K=256, iter_EM=10 (9 EM iterations + final E-step).

#define BN     4
#define HH     256
#define NN     (HH*HH)      // 65536 pixels
#define CC     20
#define KGRID  16
#define KK     (KGRID*KGRID)
#define CELLSZ 16
#define PSTR   260          // padded stride (floats): 260*4B = 65*16B keeps float4 align per row

// Scratch (device globals: no allocation allowed)
__device__ float g_mean[BN * KK * CC];
__device__ float g_partA[BN * KK * 9 * 21];
__device__ float g_partB[BN * KK * 9 * 21];

// ---------------------------------------------------------------------------
// INIT: mean of features within each initial 16x16 cell. grid=(K,B), 256 thr.
// ---------------------------------------------------------------------------
__global__ __launch_bounds__(256) void ssn_init_mean(const float* __restrict__ feat) {
    const int b = blockIdx.y, cell = blockIdx.x, t = threadIdx.x;
    const int py = cell >> 4, px = cell & 15;
    const int r = t >> 4, cc = t & 15;
    const int n = (py * CELLSZ + r) * HH + px * CELLSZ + cc;

    const float4* fp = reinterpret_cast<const float4*>(feat + (size_t)(b * NN + n) * CC);
    float f[CC];
    {
        float4 v;
        v = fp[0]; f[0]=v.x; f[1]=v.y; f[2]=v.z; f[3]=v.w;
        v = fp[1]; f[4]=v.x; f[5]=v.y; f[6]=v.z; f[7]=v.w;
        v = fp[2]; f[8]=v.x; f[9]=v.y; f[10]=v.z; f[11]=v.w;
        v = fp[3]; f[12]=v.x; f[13]=v.y; f[14]=v.z; f[15]=v.w;
        v = fp[4]; f[16]=v.x; f[17]=v.y; f[18]=v.z; f[19]=v.w;
    }

    __shared__ float ssum[CC];
    if (t < CC) ssum[t] = 0.0f;
    __syncthreads();

    const int lane = t & 31;
    #pragma unroll
    for (int c = 0; c < CC; ++c) {
        float v = f[c];
        #pragma unroll
        for (int off = 16; off > 0; off >>= 1)
            v += __shfl_xor_sync(0xffffffffu, v, off);
        if (lane == 0) atomicAdd(&ssum[c], v);
    }
    __syncthreads();
    if (t < CC) g_mean[(b * KK + cell) * CC + t] = ssum[t] * (1.0f / 256.0f);
}

// ---------------------------------------------------------------------------
// EM iteration (fused mean-finalize + E-step + M-step partial sums).
// mode: 0 = read g_mean (first iter), write g_partA
//       1 = read g_partA, write g_partB
//       2 = read g_partB, write g_partA
// grid=(K,B) blocks of 256 (block = one 16x16 cell of one batch).
// ---------------------------------------------------------------------------
__global__ __launch_bounds__(256) void ssn_em_iter(const float* __restrict__ feat, int mode) {
    __shared__ __align__(16) float p_s[9 * PSTR];     // p_s[j][pix]   (float4-read)
    __shared__ __align__(16) float f_s[CC * PSTR];    // f_s[c][pix]   (float4-read)
    __shared__ float mean_s[9 * CC];
    __shared__ float msq_s[9];
    __shared__ float raw_s[9 * 21 + 3];

    const int b = blockIdx.y, cell = blockIdx.x, t = threadIdx.x;
    const int py = cell >> 4, px = cell & 15;

    // -------- prologue: assemble the 9 neighbor-superpixel means --------
    if (mode == 0) {
        if (t < 9 * CC) {
            const int j = t / CC, c = t % CC;
            const int ky = py + j / 3 - 1, kx = px + j % 3 - 1;
            float m = 0.0f;
            if (ky >= 0 && ky < KGRID && kx >= 0 && kx < KGRID)
                m = g_mean[(b * KK + ky * KGRID + kx) * CC + c];
            mean_s[t] = m;
        }
    } else {
        const float* __restrict__ src = (mode == 1) ? g_partA : g_partB;
        if (t < 9 * 21) {
            const int j = t / 21, c = t % 21;
            const int ky = py + j / 3 - 1, kx = px + j % 3 - 1;
            float s = 0.0f;
            if (ky >= 0 && ky < KGRID && kx >= 0 && kx < KGRID) {
                #pragma unroll
                for (int dy = -1; dy <= 1; ++dy)
                    #pragma unroll
                    for (int dx = -1; dx <= 1; ++dx) {
                        const int cy = ky + dy, cx = kx + dx;
                        if (cy >= 0 && cy < KGRID && cx >= 0 && cx < KGRID) {
                            const int jj = (ky - cy + 1) * 3 + (kx - cx + 1);
                            s += src[((b * KK + cy * KGRID + cx) * 9 + jj) * 21 + c];
                        }
                    }
            }
            raw_s[t] = s;
        }
        __syncthreads();
        if (t < 9 * CC) {
            const int j = t / CC, c = t % CC;
            mean_s[t] = raw_s[j * 21 + c] / fmaxf(raw_s[j * 21 + 20], 1e-12f);
        }
    }
    __syncthreads();
    if (t < 9) {
        float s = 0.0f;
        #pragma unroll
        for (int c = 0; c < CC; ++c) { const float m = mean_s[t * CC + c]; s += m * m; }
        msq_s[t] = s;
    }
    __syncthreads();

    // -------- E-step: one pixel per thread --------
    const int r = t >> 4, cc2 = t & 15;
    const int n = (py * CELLSZ + r) * HH + px * CELLSZ + cc2;
    const float4* fp = reinterpret_cast<const float4*>(feat + (size_t)(b * NN + n) * CC);
    float f[CC];
    {
        float4 v;
        v = fp[0]; f[0]=v.x; f[1]=v.y; f[2]=v.z; f[3]=v.w;
        v = fp[1]; f[4]=v.x; f[5]=v.y; f[6]=v.z; f[7]=v.w;
        v = fp[2]; f[8]=v.x; f[9]=v.y; f[10]=v.z; f[11]=v.w;
        v = fp[3]; f[12]=v.x; f[13]=v.y; f[14]=v.z; f[15]=v.w;
        v = fp[4]; f[16]=v.x; f[17]=v.y; f[18]=v.z; f[19]=v.w;
    }
    float fsq = 0.0f;
    #pragma unroll
    for (int c = 0; c < CC; ++c) fsq = fmaf(f[c], f[c], fsq);

    float d[9];
    float dmin = 1e30f;
    #pragma unroll
    for (int j = 0; j < 9; ++j) {
        const int ky = py + j / 3 - 1, kx = px + j % 3 - 1;
        if (ky >= 0 && ky < KGRID && kx >= 0 && kx < KGRID) {
            float dot = 0.0f;
            #pragma unroll
            for (int c = 0; c < CC; ++c) dot = fmaf(f[c], mean_s[j * CC + c], dot);
            d[j] = fsq - 2.0f * dot + msq_s[j];
            dmin = fminf(dmin, d[j]);
        } else {
            d[j] = 1e30f;
        }
    }
    float p[9], denom = 0.0f;
    #pragma unroll
    for (int j = 0; j < 9; ++j) {
        p[j] = (d[j] < 1e29f) ? __expf(dmin - d[j]) : 0.0f;
        denom += p[j];
    }
    const float inv = 1.0f / denom;   // denom >= 1 (argmin contributes exp(0)=1)
    #pragma unroll
    for (int j = 0; j < 9; ++j) p_s[j * PSTR + t] = p[j] * inv;
    #pragma unroll
    for (int c = 0; c < CC; ++c) f_s[c * PSTR + t] = f[c];
    __syncthreads();

    // -------- M-step partial: 189 outputs (9 neighbors x (20 wsum + psum)) --------
    float* __restrict__ dst = (mode == 1) ? g_partB : g_partA;
    if (t < 189) {
        int c, j;
        if (t < 180) { c = t / 9; j = t % 9; } else { c = 20; j = t - 180; }
        const float4* pv = reinterpret_cast<const float4*>(p_s + j * PSTR);
        float a0 = 0.f, a1 = 0.f, a2 = 0.f, a3 = 0.f;
        if (c < CC) {
            const float4* fv = reinterpret_cast<const float4*>(f_s + c * PSTR);
            #pragma unroll 4
            for (int i = 0; i < 64; i += 4) {
                float4 pA = pv[i+0], fA = fv[i+0];
                float4 pB = pv[i+1], fB = fv[i+1];
                float4 pC = pv[i+2], fC = fv[i+2];
                float4 pD = pv[i+3], fD = fv[i+3];
                a0 = fmaf(pA.x, fA.x, fmaf(pA.y, fA.y, fmaf(pA.z, fA.z, fmaf(pA.w, fA.w, a0))));
                a1 = fmaf(pB.x, fB.x, fmaf(pB.y, fB.y, fmaf(pB.z, fB.z, fmaf(pB.w, fB.w, a1))));
                a2 = fmaf(pC.x, fC.x, fmaf(pC.y, fC.y, fmaf(pC.z, fC.z, fmaf(pC.w, fC.w, a2))));
                a3 = fmaf(pD.x, fD.x, fmaf(pD.y, fD.y, fmaf(pD.z, fD.z, fmaf(pD.w, fD.w, a3))));
            }
        } else {
            #pragma unroll 4
            for (int i = 0; i < 64; i += 4) {
                float4 pA = pv[i+0], pB = pv[i+1], pC = pv[i+2], pD = pv[i+3];
                a0 += (pA.x + pA.y) + (pA.z + pA.w);
                a1 += (pB.x + pB.y) + (pB.z + pB.w);
                a2 += (pC.x + pC.y) + (pC.z + pC.w);
                a3 += (pD.x + pD.y) + (pD.z + pD.w);
            }
        }
        dst[((b * KK + cell) * 9 + j) * 21 + c] = (a0 + a1) + (a2 + a3);
    }
}

// ---------------------------------------------------------------------------
// FINAL: finalize mean from g_partA, E-step, expand to dense [B,N,K] output.
// grid=(K,B), 256 threads.
// ---------------------------------------------------------------------------
__global__ __launch_bounds__(256) void ssn_final(const float* __restrict__ feat,
                                                 float* __restrict__ out) {
    __shared__ __align__(16) float p_s[256 * 9];      // p_s[pix][j] (scalar reads)
    __shared__ float mean_s[9 * CC];
    __shared__ float msq_s[9];
    __shared__ float raw_s[9 * 21 + 3];

    const int b = blockIdx.y, cell = blockIdx.x, t = threadIdx.x;
    const int py = cell >> 4, px = cell & 15;

    // mean finalize from g_partA
    if (t < 9 * 21) {
        const int j = t / 21, c = t % 21;
        const int ky = py + j / 3 - 1, kx = px + j % 3 - 1;
        float s = 0.0f;
        if (ky >= 0 && ky < KGRID && kx >= 0 && kx < KGRID) {
            #pragma unroll
            for (int dy = -1; dy <= 1; ++dy)
                #pragma unroll
                for (int dx = -1; dx <= 1; ++dx) {
                    const int cy = ky + dy, cx = kx + dx;
                    if (cy >= 0 && cy < KGRID && cx >= 0 && cx < KGRID) {
                        const int jj = (ky - cy + 1) * 3 + (kx - cx + 1);
                        s += g_partA[((b * KK + cy * KGRID + cx) * 9 + jj) * 21 + c];
                    }
                }
        }
        raw_s[t] = s;
    }
    __syncthreads();
    if (t < 9 * CC) {
        const int j = t / CC, c = t % CC;
        mean_s[t] = raw_s[j * 21 + c] / fmaxf(raw_s[j * 21 + 20], 1e-12f);
    }
    __syncthreads();
    if (t < 9) {
        float s = 0.0f;
        #pragma unroll
        for (int c = 0; c < CC; ++c) { const float m = mean_s[t * CC + c]; s += m * m; }
        msq_s[t] = s;
    }
    __syncthreads();

    // E-step for this thread's pixel
    const int r = t >> 4, cc2 = t & 15;
    const int n = (py * CELLSZ + r) * HH + px * CELLSZ + cc2;
    const float4* fp = reinterpret_cast<const float4*>(feat + (size_t)(b * NN + n) * CC);
    float f[CC];
    {
        float4 v;
        v = fp[0]; f[0]=v.x; f[1]=v.y; f[2]=v.z; f[3]=v.w;
        v = fp[1]; f[4]=v.x; f[5]=v.y; f[6]=v.z; f[7]=v.w;
        v = fp[2]; f[8]=v.x; f[9]=v.y; f[10]=v.z; f[11]=v.w;
        v = fp[3]; f[12]=v.x; f[13]=v.y; f[14]=v.z; f[15]=v.w;
        v = fp[4]; f[16]=v.x; f[17]=v.y; f[18]=v.z; f[19]=v.w;
    }
    float fsq = 0.0f;
    #pragma unroll
    for (int c = 0; c < CC; ++c) fsq = fmaf(f[c], f[c], fsq);

    float d[9];
    float dmin = 1e30f;
    #pragma unroll
    for (int j = 0; j < 9; ++j) {
        const int ky = py + j / 3 - 1, kx = px + j % 3 - 1;
        if (ky >= 0 && ky < KGRID && kx >= 0 && kx < KGRID) {
            float dot = 0.0f;
            #pragma unroll
            for (int c = 0; c < CC; ++c) dot = fmaf(f[c], mean_s[j * CC + c], dot);
            d[j] = fsq - 2.0f * dot + msq_s[j];
            dmin = fminf(dmin, d[j]);
        } else {
            d[j] = 1e30f;
        }
    }
    float p[9], denom = 0.0f;
    #pragma unroll
    for (int j = 0; j < 9; ++j) {
        p[j] = (d[j] < 1e29f) ? __expf(dmin - d[j]) : 0.0f;
        denom += p[j];
    }
    const float inv = 1.0f / denom;
    #pragma unroll
    for (int j = 0; j < 9; ++j) p_s[t * 9 + j] = p[j] * inv;
    __syncthreads();

    // Dense expansion: 64 iterations x (4 pixels x 64 float4s) = 256 pixels x 256 k
    const int sub = t >> 6;        // which of the 4 pixels this thread serves
    const int kq  = t & 63;        // float4 index within the k-row
    const int k0  = kq * 4;
    const int gy  = k0 >> 4;       // constant across the float4 (k0 % 16 <= 12)
    const int dy  = gy - py;
    const bool rowok = (dy >= -1 && dy <= 1);
    const int jbase = (dy + 1) * 3;
    const int gx0 = k0 & 15;

    for (int it = 0; it < 64; ++it) {
        const int pix = it * 4 + sub;
        const int rr = pix >> 4, cpx = pix & 15;
        const int n2 = (py * CELLSZ + rr) * HH + px * CELLSZ + cpx;
        const float* pr = &p_s[pix * 9];
        float4 v;
        {
            const int dx = gx0 + 0 - px;
            v.x = (rowok && dx >= -1 && dx <= 1) ? pr[jbase + dx + 1] : 0.0f;
        }
        {
            const int dx = gx0 + 1 - px;
            v.y = (rowok && dx >= -1 && dx <= 1) ? pr[jbase + dx + 1] : 0.0f;
        }
        {
            const int dx = gx0 + 2 - px;
            v.z = (rowok && dx >= -1 && dx <= 1) ? pr[jbase + dx + 1] : 0.0f;
        }
        {
            const int dx = gx0 + 3 - px;
            v.w = (rowok && dx >= -1 && dx <= 1) ? pr[jbase + dx + 1] : 0.0f;
        }
        reinterpret_cast<float4*>(out + (size_t)(b * NN + n2) * KK)[kq] = v;
    }
}

// ---------------------------------------------------------------------------
extern "C" void kernel_launch(void* const* d_in, const int* in_sizes, int n_in,
                              void* d_out, int out_size) {
    const float* feat = (const float*)d_in[0];
    float* out = (float*)d_out;
    (void)in_sizes; (void)n_in; (void)out_size;

    dim3 grid(KK, BN);

    ssn_init_mean<<<grid, 256>>>(feat);
    // iter 1: uses init mean, writes partA
    ssn_em_iter<<<grid, 256>>>(feat, 0);
    // iters 2..9: ping-pong A->B, B->A (ends with partials in A)
    for (int i = 0; i < 4; ++i) {
        ssn_em_iter<<<grid, 256>>>(feat, 1);
        ssn_em_iter<<<grid, 256>>>(feat, 2);
    }
    // final E-step from partA, dense output
    ssn_final<<<grid, 256>>>(feat, out);
}

// round 7
// speedup vs baseline: 1.3723x; 1.3723x over previous
#include <cuda_runtime.h>

// SSN superpixel EM, sparse 9-neighborhood formulation.
// B=4, H=W=256, C=20, 16x16 superpixel grid, cell=16x16, K=256, 10 EM iters.

#define BN     4
#define HH     256
#define NN     (HH*HH)      // 65536 pixels
#define CC     20
#define KGRID  16
#define KK     (KGRID*KGRID)
#define CELLSZ 16
#define PS     257          // odd smem stride: conflict-free column access

// Scratch (device globals: no allocation allowed)
__device__ float g_mean[BN * KK * CC];
__device__ float g_partA[BN * KK * 9 * 21];
__device__ float g_partB[BN * KK * 9 * 21];

// ---------------------------------------------------------------------------
// INIT: mean of features within each initial 16x16 cell. grid=(K,B), 256 thr.
// ---------------------------------------------------------------------------
__global__ __launch_bounds__(256) void ssn_init_mean(const float* __restrict__ feat) {
    const int b = blockIdx.y, cell = blockIdx.x, t = threadIdx.x;
    const int py = cell >> 4, px = cell & 15;
    const int r = t >> 4, cc = t & 15;
    const int n = (py * CELLSZ + r) * HH + px * CELLSZ + cc;

    const float4* fp = reinterpret_cast<const float4*>(feat + (size_t)(b * NN + n) * CC);
    float f[CC];
    {
        float4 v;
        v = fp[0]; f[0]=v.x; f[1]=v.y; f[2]=v.z; f[3]=v.w;
        v = fp[1]; f[4]=v.x; f[5]=v.y; f[6]=v.z; f[7]=v.w;
        v = fp[2]; f[8]=v.x; f[9]=v.y; f[10]=v.z; f[11]=v.w;
        v = fp[3]; f[12]=v.x; f[13]=v.y; f[14]=v.z; f[15]=v.w;
        v = fp[4]; f[16]=v.x; f[17]=v.y; f[18]=v.z; f[19]=v.w;
    }

    __shared__ float ssum[CC];
    if (t < CC) ssum[t] = 0.0f;
    __syncthreads();

    const int lane = t & 31;
    #pragma unroll
    for (int c = 0; c < CC; ++c) {
        float v = f[c];
        #pragma unroll
        for (int off = 16; off > 0; off >>= 1)
            v += __shfl_xor_sync(0xffffffffu, v, off);
        if (lane == 0) atomicAdd(&ssum[c], v);
    }
    __syncthreads();
    if (t < CC) g_mean[(b * KK + cell) * CC + t] = ssum[t] * (1.0f / 256.0f);
}

// ---------------------------------------------------------------------------
// EM iteration (fused mean-finalize + E-step + tiled M-step partial sums).
// mode: 0 = read g_mean, write g_partA
//       1 = read g_partA, write g_partB
//       2 = read g_partB, write g_partA
// grid=(K,B) blocks of 256 (block = one 16x16 cell of one batch).
// ---------------------------------------------------------------------------
__global__ __launch_bounds__(256, 5) void ssn_em_iter(const float* __restrict__ feat, int mode) {
    __shared__ float p_s[9 * PS];     // p_s[j][pix]
    __shared__ float f_s[CC * PS];    // f_s[c][pix]
    __shared__ float mean_s[9 * CC];
    __shared__ float msq_s[9];
    __shared__ float raw_s[9 * 21 + 3];

    const int b = blockIdx.y, cell = blockIdx.x, t = threadIdx.x;
    const int py = cell >> 4, px = cell & 15;

    // -------- prologue: assemble the 9 neighbor-superpixel means --------
    if (mode == 0) {
        if (t < 9 * CC) {
            const int j = t / CC, c = t % CC;
            const int ky = py + j / 3 - 1, kx = px + j % 3 - 1;
            float m = 0.0f;
            if (ky >= 0 && ky < KGRID && kx >= 0 && kx < KGRID)
                m = g_mean[(b * KK + ky * KGRID + kx) * CC + c];
            mean_s[t] = m;
        }
    } else {
        const float* __restrict__ src = (mode == 1) ? g_partA : g_partB;
        if (t < 9 * 21) {
            const int j = t / 21, c = t % 21;
            const int ky = py + j / 3 - 1, kx = px + j % 3 - 1;
            float s = 0.0f;
            if (ky >= 0 && ky < KGRID && kx >= 0 && kx < KGRID) {
                #pragma unroll
                for (int dy = -1; dy <= 1; ++dy)
                    #pragma unroll
                    for (int dx = -1; dx <= 1; ++dx) {
                        const int cy = ky + dy, cx = kx + dx;
                        if (cy >= 0 && cy < KGRID && cx >= 0 && cx < KGRID) {
                            const int jj = (ky - cy + 1) * 3 + (kx - cx + 1);
                            s += src[((b * KK + cy * KGRID + cx) * 9 + jj) * 21 + c];
                        }
                    }
            }
            raw_s[t] = s;
        }
        __syncthreads();
        if (t < 9 * CC) {
            const int j = t / CC, c = t % CC;
            mean_s[t] = raw_s[j * 21 + c] / fmaxf(raw_s[j * 21 + 20], 1e-12f);
        }
    }
    __syncthreads();
    if (t < 9) {
        float s = 0.0f;
        #pragma unroll
        for (int c = 0; c < CC; ++c) { const float m = mean_s[t * CC + c]; s += m * m; }
        msq_s[t] = s;
    }
    __syncthreads();

    // -------- E-step: one pixel per thread --------
    const int r = t >> 4, cc2 = t & 15;
    const int n = (py * CELLSZ + r) * HH + px * CELLSZ + cc2;
    const float4* fp = reinterpret_cast<const float4*>(feat + (size_t)(b * NN + n) * CC);
    float f[CC];
    {
        float4 v;
        v = fp[0]; f[0]=v.x; f[1]=v.y; f[2]=v.z; f[3]=v.w;
        v = fp[1]; f[4]=v.x; f[5]=v.y; f[6]=v.z; f[7]=v.w;
        v = fp[2]; f[8]=v.x; f[9]=v.y; f[10]=v.z; f[11]=v.w;
        v = fp[3]; f[12]=v.x; f[13]=v.y; f[14]=v.z; f[15]=v.w;
        v = fp[4]; f[16]=v.x; f[17]=v.y; f[18]=v.z; f[19]=v.w;
    }
    float fsq = 0.0f;
    #pragma unroll
    for (int c = 0; c < CC; ++c) fsq = fmaf(f[c], f[c], fsq);

    float d[9];
    float dmin = 1e30f;
    #pragma unroll
    for (int j = 0; j < 9; ++j) {
        const int ky = py + j / 3 - 1, kx = px + j % 3 - 1;
        if (ky >= 0 && ky < KGRID && kx >= 0 && kx < KGRID) {
            float dot = 0.0f;
            #pragma unroll
            for (int c = 0; c < CC; ++c) dot = fmaf(f[c], mean_s[j * CC + c], dot);
            d[j] = fsq - 2.0f * dot + msq_s[j];
            dmin = fminf(dmin, d[j]);
        } else {
            d[j] = 1e30f;
        }
    }
    float p[9], denom = 0.0f;
    #pragma unroll
    for (int j = 0; j < 9; ++j) {
        p[j] = (d[j] < 1e29f) ? __expf(dmin - d[j]) : 0.0f;
        denom += p[j];
    }
    const float inv = 1.0f / denom;   // denom >= 1 (argmin contributes exp(0)=1)
    #pragma unroll
    for (int j = 0; j < 9; ++j) p_s[j * PS + t] = p[j] * inv;
    #pragma unroll
    for (int c = 0; c < CC; ++c) f_s[c * PS + t] = f[c];
    __syncthreads();

    // -------- M-step (tiled): 9 tiles of 3x7 (j,c), 16 pixel-groups each.
    // Thread (tile, g) accumulates 21 outputs over 16 pixels; the 16 groups
    // of a tile live in one half-warp -> butterfly reduce, no extra smem.
    // Output layout: [cell][j][c] with c==20 == posterior sum (f := 1).
    float* __restrict__ dst = (mode == 1) ? g_partB : g_partA;
    if (t < 160) {
        const int tile = (t < 144) ? (t >> 4) : 8;  // lanes 16..31 of warp 4 duplicate tile 8
        const int g = t & 15;
        const int j0 = (tile / 3) * 3;
        const int c0 = (tile % 3) * 7;

        float acc[21];
        #pragma unroll
        for (int o = 0; o < 21; ++o) acc[o] = 0.0f;

        #pragma unroll 4
        for (int ii = 0; ii < 16; ++ii) {
            const int pix = ii * 16 + g;
            const float pj0 = p_s[(j0 + 0) * PS + pix];
            const float pj1 = p_s[(j0 + 1) * PS + pix];
            const float pj2 = p_s[(j0 + 2) * PS + pix];
            float fc[7];
            #pragma unroll
            for (int cc = 0; cc < 7; ++cc) {
                const int c = c0 + cc;
                fc[cc] = (c < CC) ? f_s[c * PS + pix] : 1.0f;
            }
            #pragma unroll
            for (int cc = 0; cc < 7; ++cc) {
                acc[cc]      = fmaf(pj0, fc[cc], acc[cc]);
                acc[7 + cc]  = fmaf(pj1, fc[cc], acc[7 + cc]);
                acc[14 + cc] = fmaf(pj2, fc[cc], acc[14 + cc]);
            }
        }
        // half-warp butterfly (offsets < 16 stay within the 16-lane group)
        #pragma unroll
        for (int o = 0; o < 21; ++o) {
            #pragma unroll
            for (int off = 8; off >= 1; off >>= 1)
                acc[o] += __shfl_xor_sync(0xffffffffu, acc[o], off);
        }
        if (t < 144) {
            const int base = ((b * KK + cell) * 9 + j0) * 21 + c0;
            {   // output o = g (0..15)
                const int jj = g / 7, cc = g % 7;
                dst[base + jj * 21 + cc] = acc[g];
            }
            if (g < 5) {   // output o = g+16 (16..20)
                const int o = g + 16;
                const int jj = o / 7, cc = o % 7;
                dst[base + jj * 21 + cc] = acc[o];
            }
        }
    }
}

// ---------------------------------------------------------------------------
// FINAL: finalize mean from g_partA, E-step, expand to dense [B,N,K] output.
// grid=(K,B), 256 threads.
// ---------------------------------------------------------------------------
__global__ __launch_bounds__(256) void ssn_final(const float* __restrict__ feat,
                                                 float* __restrict__ out) {
    __shared__ float p_s[256 * 9];      // p_s[pix][j]
    __shared__ float mean_s[9 * CC];
    __shared__ float msq_s[9];
    __shared__ float raw_s[9 * 21 + 3];

    const int b = blockIdx.y, cell = blockIdx.x, t = threadIdx.x;
    const int py = cell >> 4, px = cell & 15;

    // mean finalize from g_partA
    if (t < 9 * 21) {
        const int j = t / 21, c = t % 21;
        const int ky = py + j / 3 - 1, kx = px + j % 3 - 1;
        float s = 0.0f;
        if (ky >= 0 && ky < KGRID && kx >= 0 && kx < KGRID) {
            #pragma unroll
            for (int dy = -1; dy <= 1; ++dy)
                #pragma unroll
                for (int dx = -1; dx <= 1; ++dx) {
                    const int cy = ky + dy, cx = kx + dx;
                    if (cy >= 0 && cy < KGRID && cx >= 0 && cx < KGRID) {
                        const int jj = (ky - cy + 1) * 3 + (kx - cx + 1);
                        s += g_partA[((b * KK + cy * KGRID + cx) * 9 + jj) * 21 + c];
                    }
                }
        }
        raw_s[t] = s;
    }
    __syncthreads();
    if (t < 9 * CC) {
        const int j = t / CC, c = t % CC;
        mean_s[t] = raw_s[j * 21 + c] / fmaxf(raw_s[j * 21 + 20], 1e-12f);
    }
    __syncthreads();
    if (t < 9) {
        float s = 0.0f;
        #pragma unroll
        for (int c = 0; c < CC; ++c) { const float m = mean_s[t * CC + c]; s += m * m; }
        msq_s[t] = s;
    }
    __syncthreads();

    // E-step for this thread's pixel
    const int r = t >> 4, cc2 = t & 15;
    const int n = (py * CELLSZ + r) * HH + px * CELLSZ + cc2;
    const float4* fp = reinterpret_cast<const float4*>(feat + (size_t)(b * NN + n) * CC);
    float f[CC];
    {
        float4 v;
        v = fp[0]; f[0]=v.x; f[1]=v.y; f[2]=v.z; f[3]=v.w;
        v = fp[1]; f[4]=v.x; f[5]=v.y; f[6]=v.z; f[7]=v.w;
        v = fp[2]; f[8]=v.x; f[9]=v.y; f[10]=v.z; f[11]=v.w;
        v = fp[3]; f[12]=v.x; f[13]=v.y; f[14]=v.z; f[15]=v.w;
        v = fp[4]; f[16]=v.x; f[17]=v.y; f[18]=v.z; f[19]=v.w;
    }
    float fsq = 0.0f;
    #pragma unroll
    for (int c = 0; c < CC; ++c) fsq = fmaf(f[c], f[c], fsq);

    float d[9];
    float dmin = 1e30f;
    #pragma unroll
    for (int j = 0; j < 9; ++j) {
        const int ky = py + j / 3 - 1, kx = px + j % 3 - 1;
        if (ky >= 0 && ky < KGRID && kx >= 0 && kx < KGRID) {
            float dot = 0.0f;
            #pragma unroll
            for (int c = 0; c < CC; ++c) dot = fmaf(f[c], mean_s[j * CC + c], dot);
            d[j] = fsq - 2.0f * dot + msq_s[j];
            dmin = fminf(dmin, d[j]);
        } else {
            d[j] = 1e30f;
        }
    }
    float p[9], denom = 0.0f;
    #pragma unroll
    for (int j = 0; j < 9; ++j) {
        p[j] = (d[j] < 1e29f) ? __expf(dmin - d[j]) : 0.0f;
        denom += p[j];
    }
    const float inv = 1.0f / denom;
    #pragma unroll
    for (int j = 0; j < 9; ++j) p_s[t * 9 + j] = p[j] * inv;
    __syncthreads();

    // Dense expansion: 64 iterations x (4 pixels x 64 float4s) = 256 pixels x 256 k
    const int sub = t >> 6;        // which of the 4 pixels this thread serves
    const int kq  = t & 63;        // float4 index within the k-row
    const int k0  = kq * 4;
    const int gy  = k0 >> 4;       // constant across the float4 (k0 % 16 <= 12)
    const int dy  = gy - py;
    const bool rowok = (dy >= -1 && dy <= 1);
    const int jbase = (dy + 1) * 3;
    const int gx0 = k0 & 15;

    for (int it = 0; it < 64; ++it) {
        const int pix = it * 4 + sub;
        const int rr = pix >> 4, cpx = pix & 15;
        const int n2 = (py * CELLSZ + rr) * HH + px * CELLSZ + cpx;
        const float* pr = &p_s[pix * 9];
        float4 v;
        {
            const int dx = gx0 + 0 - px;
            v.x = (rowok && dx >= -1 && dx <= 1) ? pr[jbase + dx + 1] : 0.0f;
        }
        {
            const int dx = gx0 + 1 - px;
            v.y = (rowok && dx >= -1 && dx <= 1) ? pr[jbase + dx + 1] : 0.0f;
        }
        {
            const int dx = gx0 + 2 - px;
            v.z = (rowok && dx >= -1 && dx <= 1) ? pr[jbase + dx + 1] : 0.0f;
        }
        {
            const int dx = gx0 + 3 - px;
            v.w = (rowok && dx >= -1 && dx <= 1) ? pr[jbase + dx + 1] : 0.0f;
        }
        reinterpret_cast<float4*>(out + (size_t)(b * NN + n2) * KK)[kq] = v;
    }
}

// ---------------------------------------------------------------------------
extern "C" void kernel_launch(void* const* d_in, const int* in_sizes, int n_in,
                              void* d_out, int out_size) {
    const float* feat = (const float*)d_in[0];
    float* out = (float*)d_out;
    (void)in_sizes; (void)n_in; (void)out_size;

    dim3 grid(KK, BN);

    ssn_init_mean<<<grid, 256>>>(feat);
    // iter 1: uses init mean, writes partA
    ssn_em_iter<<<grid, 256>>>(feat, 0);
    // iters 2..9: ping-pong A->B, B->A (ends with partials in A)
    for (int i = 0; i < 4; ++i) {
        ssn_em_iter<<<grid, 256>>>(feat, 1);
        ssn_em_iter<<<grid, 256>>>(feat, 2);
    }
    // final E-step from partA, dense output
    ssn_final<<<grid, 256>>>(feat, out);
}